// round 1
// baseline (speedup 1.0000x reference)
#include <cuda_runtime.h>
#include <math.h>

// Problem dims
#define LL    512
#define BB    2
#define DD    768
#define EDD   1536
#define NST   16
#define KCV   4
#define DTR   48
#define VV    1024
#define NTOK  (LL*BB)   // 1024 tokens, t = b*LL + l
#define NLAY  24
#define SPW   80        // DT_RANK + 2*N

// Scratch (device globals; no allocation allowed)
__device__ float g_h [NTOK*DD];
__device__ float g_xn[NTOK*DD];
__device__ float g_ug[NTOK*2*EDD];
__device__ float g_uc[NTOK*EDD];
__device__ float g_sp[NTOK*SPW];
__device__ float g_dt[NTOK*EDD];
__device__ float g_y [NTOK*EDD];

// ---------------------------------------------------------------------------
// Embedding gather: h[t,:] = embed[src[l,b],:],  t = b*L + l
// ---------------------------------------------------------------------------
__global__ void embed_kernel(const int* __restrict__ src,
                             const float* __restrict__ emb,
                             float* __restrict__ h)
{
    int t = blockIdx.x;
    int b = t >> 9, l = t & (LL - 1);
    int id = src[l * BB + b];
    const float* er = emb + (size_t)id * DD;
    float* hr = h + (size_t)t * DD;
    for (int i = threadIdx.x; i < DD; i += 256) hr[i] = er[i];
}

// ---------------------------------------------------------------------------
// RMSNorm: out = x * rsqrt(mean(x^2)+1e-5) * w   (per token, D=768)
// ---------------------------------------------------------------------------
__global__ void rmsnorm_kernel(const float* __restrict__ x,
                               const float* __restrict__ w,
                               float* __restrict__ out)
{
    int t = blockIdx.x;
    const float* xr = x + (size_t)t * DD;
    float s = 0.f;
    for (int i = threadIdx.x; i < DD; i += 256) { float v = xr[i]; s += v * v; }
    __shared__ float red[256];
    red[threadIdx.x] = s;
    __syncthreads();
    for (int off = 128; off > 0; off >>= 1) {
        if (threadIdx.x < off) red[threadIdx.x] += red[threadIdx.x + off];
        __syncthreads();
    }
    float scale = rsqrtf(red[0] / (float)DD + 1e-5f);
    float* orow = out + (size_t)t * DD;
    for (int i = threadIdx.x; i < DD; i += 256) orow[i] = xr[i] * scale * w[i];
}

// ---------------------------------------------------------------------------
// GEMM (NT): C[M,N] = A[M,K] * W[N,K]^T.  A row-stride lda, W row-stride ldw.
// M = 1024 always (multiple of 128). K multiple of 8. N arbitrary (guarded).
// mode 0: store; mode 1: += (residual); mode 2: permuted logits store.
// 128x128x8 tiles, 256 threads, 8x8 accum per thread.
// ---------------------------------------------------------------------------
__global__ __launch_bounds__(256) void gemm_nt(
    const float* __restrict__ A, int lda,
    const float* __restrict__ W, int ldw,
    float* __restrict__ C,
    int N, int K, int mode)
{
    __shared__ float As[8][132];
    __shared__ float Ws[8][132];
    const int tid = threadIdx.x;
    const int bm = blockIdx.y * 128;
    const int bn = blockIdx.x * 128;
    const int lr = tid >> 1;            // 0..127
    const int lc = (tid & 1) << 2;      // 0 or 4
    const int tr = (tid >> 4) << 3;     // 0..120 step 8
    const int tc = (tid & 15) << 3;     // 0..120 step 8

    float acc[8][8];
#pragma unroll
    for (int i = 0; i < 8; i++)
#pragma unroll
        for (int j = 0; j < 8; j++) acc[i][j] = 0.f;

    const float* Ap = A + (size_t)(bm + lr) * lda + lc;
    const bool wok = (bn + lr) < N;
    const float* Wp = W + (size_t)(bn + lr) * ldw + lc;

    for (int k0 = 0; k0 < K; k0 += 8) {
        float4 a4 = *(const float4*)(Ap + k0);
        float4 w4 = wok ? *(const float4*)(Wp + k0) : make_float4(0.f, 0.f, 0.f, 0.f);
        __syncthreads();
        As[lc + 0][lr] = a4.x; As[lc + 1][lr] = a4.y;
        As[lc + 2][lr] = a4.z; As[lc + 3][lr] = a4.w;
        Ws[lc + 0][lr] = w4.x; Ws[lc + 1][lr] = w4.y;
        Ws[lc + 2][lr] = w4.z; Ws[lc + 3][lr] = w4.w;
        __syncthreads();
#pragma unroll
        for (int k = 0; k < 8; k++) {
            float4 x0 = *(const float4*)&As[k][tr];
            float4 x1 = *(const float4*)&As[k][tr + 4];
            float4 y0 = *(const float4*)&Ws[k][tc];
            float4 y1 = *(const float4*)&Ws[k][tc + 4];
            float av[8] = {x0.x, x0.y, x0.z, x0.w, x1.x, x1.y, x1.z, x1.w};
            float bv[8] = {y0.x, y0.y, y0.z, y0.w, y1.x, y1.y, y1.z, y1.w};
#pragma unroll
            for (int i = 0; i < 8; i++)
#pragma unroll
                for (int j = 0; j < 8; j++)
                    acc[i][j] += av[i] * bv[j];
        }
    }

#pragma unroll
    for (int i = 0; i < 8; i++) {
        int row = bm + tr + i;
#pragma unroll
        for (int j = 0; j < 8; j++) {
            int col = bn + tc + j;
            if (col < N) {
                if (mode == 0) {
                    C[(size_t)row * N + col] = acc[i][j];
                } else if (mode == 1) {
                    C[(size_t)row * N + col] += acc[i][j];
                } else {
                    // logits: row = t = b*L + l -> out[l, b, col]
                    int l = row & (LL - 1), b = row >> 9;
                    C[(size_t)l * (BB * VV) + (size_t)b * VV + col] = acc[i][j];
                }
            }
        }
    }
}

// ---------------------------------------------------------------------------
// Depthwise causal conv (K=4) + SiLU:  uc[t,e] = silu(sum_k u[b,l-3+k,e]*cw[e,k]+cb[e])
// u is the first ED of each ug row.
// ---------------------------------------------------------------------------
__global__ void conv_silu_kernel(const float* __restrict__ ug,
                                 const float* __restrict__ cw,
                                 const float* __restrict__ cb,
                                 float* __restrict__ uc)
{
    int idx = blockIdx.x * blockDim.x + threadIdx.x;
    if (idx >= NTOK * EDD) return;
    int t = idx / EDD, e = idx - t * EDD;
    int l = t & (LL - 1);
    const float* base = ug + (size_t)t * (2 * EDD) + e;
    float4 w = *(const float4*)(cw + (size_t)e * KCV);
    float acc = cb[e];
    acc += (l >= 3 ? base[-3 * 2 * EDD] : 0.f) * w.x;
    acc += (l >= 2 ? base[-2 * 2 * EDD] : 0.f) * w.y;
    acc += (l >= 1 ? base[-1 * 2 * EDD] : 0.f) * w.z;
    acc += base[0] * w.w;
    float s = 1.f / (1.f + __expf(-acc));
    uc[idx] = acc * s;
}

// ---------------------------------------------------------------------------
// dt activation: dt = softplus(dt_raw + dt_b[e])
// ---------------------------------------------------------------------------
__global__ void dtact_kernel(float* __restrict__ dtb, const float* __restrict__ bias)
{
    int idx = blockIdx.x * blockDim.x + threadIdx.x;
    if (idx >= NTOK * EDD) return;
    int e = idx % EDD;
    float x = dtb[idx] + bias[e];
    dtb[idx] = (x > 15.f) ? x : log1pf(__expf(x));
}

// ---------------------------------------------------------------------------
// Selective scan, fused (+ u*Dp) * silu(g) epilogue.
// Thread layout: 4 threads per (b,e), each owns 4 of the 16 N-states.
// g = global thread id: b = g/6144, e = (g%6144)/4, q = g%4.
// Lanes are q-contiguous -> shfl_xor 1,2 reduces over the N-split.
// ---------------------------------------------------------------------------
__global__ __launch_bounds__(128) void scan_kernel(
    const float* __restrict__ dt,    // [NTOK, ED]
    const float* __restrict__ uc,    // [NTOK, ED]
    const float* __restrict__ sp,    // [NTOK, 80]  (dt_r | B | C)
    const float* __restrict__ ug,    // [NTOK, 2ED] (g at +ED)
    const float* __restrict__ A_log, // [ED, 16] for this layer
    const float* __restrict__ Dp,    // [ED]
    float* __restrict__ y)           // [NTOK, ED]
{
    int g = blockIdx.x * blockDim.x + threadIdx.x;   // 0..12287
    int b = g / (EDD * 4);
    int r = g - b * (EDD * 4);
    int e = r >> 2;
    int q = r & 3;

    float4 al = *(const float4*)(A_log + (size_t)e * NST + q * 4);
    float a0 = -__expf(al.x), a1 = -__expf(al.y),
          a2 = -__expf(al.z), a3 = -__expf(al.w);
    float dD = Dp[e];

    float h0 = 0.f, h1 = 0.f, h2 = 0.f, h3 = 0.f;
    int t = b * LL;
    for (int l = 0; l < LL; l++, t++) {
        float dtv = __ldg(dt + (size_t)t * EDD + e);
        float u   = __ldg(uc + (size_t)t * EDD + e);
        float4 Bv = *(const float4*)(sp + (size_t)t * SPW + DTR + q * 4);
        float4 Cv = *(const float4*)(sp + (size_t)t * SPW + DTR + NST + q * 4);
        float du = dtv * u;
        h0 = __expf(dtv * a0) * h0 + du * Bv.x;
        h1 = __expf(dtv * a1) * h1 + du * Bv.y;
        h2 = __expf(dtv * a2) * h2 + du * Bv.z;
        h3 = __expf(dtv * a3) * h3 + du * Bv.w;
        float ys = h0 * Cv.x + h1 * Cv.y + h2 * Cv.z + h3 * Cv.w;
        ys += __shfl_xor_sync(0xffffffffu, ys, 1);
        ys += __shfl_xor_sync(0xffffffffu, ys, 2);
        if (q == 0) {
            float gv = __ldg(ug + (size_t)t * (2 * EDD) + EDD + e);
            float sig = 1.f / (1.f + __expf(-gv));
            y[(size_t)t * EDD + e] = (ys + u * dD) * (gv * sig);
        }
    }
}

// ---------------------------------------------------------------------------
extern "C" void kernel_launch(void* const* d_in, const int* in_sizes, int n_in,
                              void* d_out, int out_size)
{
    const int*   src     = (const int*)  d_in[0];
    const float* emb     = (const float*)d_in[1];
    const float* norm_w  = (const float*)d_in[2];
    const float* in_proj = (const float*)d_in[3];
    const float* conv_w  = (const float*)d_in[4];
    const float* conv_b  = (const float*)d_in[5];
    const float* x_proj  = (const float*)d_in[6];
    const float* dt_w    = (const float*)d_in[7];
    const float* dt_b    = (const float*)d_in[8];
    const float* A_log   = (const float*)d_in[9];
    const float* Dp      = (const float*)d_in[10];
    const float* out_prj = (const float*)d_in[11];
    const float* normf_w = (const float*)d_in[12];
    float* out = (float*)d_out;
    (void)in_sizes; (void)n_in; (void)out_size;

    float *h, *xn, *ug, *uc, *sp, *dtb, *y;
    cudaGetSymbolAddress((void**)&h,   g_h);
    cudaGetSymbolAddress((void**)&xn,  g_xn);
    cudaGetSymbolAddress((void**)&ug,  g_ug);
    cudaGetSymbolAddress((void**)&uc,  g_uc);
    cudaGetSymbolAddress((void**)&sp,  g_sp);
    cudaGetSymbolAddress((void**)&dtb, g_dt);
    cudaGetSymbolAddress((void**)&y,   g_y);

    embed_kernel<<<NTOK, 256>>>(src, emb, h);

    const dim3 gIn (2 * EDD / 128, NTOK / 128);   // N=3072
    const dim3 gXp (1,             NTOK / 128);   // N=80
    const dim3 gDt (EDD / 128,     NTOK / 128);   // N=1536
    const dim3 gOut(DD / 128,      NTOK / 128);   // N=768
    const dim3 gLog(VV / 128,      NTOK / 128);   // N=1024

    for (int lay = 0; lay < NLAY; lay++) {
        rmsnorm_kernel<<<NTOK, 256>>>(h, norm_w + (size_t)lay * DD, xn);
        gemm_nt<<<gIn, 256>>>(xn, DD,
                              in_proj + (size_t)lay * 2 * EDD * DD, DD,
                              ug, 2 * EDD, DD, 0);
        conv_silu_kernel<<<(NTOK * EDD) / 256, 256>>>(
            ug, conv_w + (size_t)lay * EDD * KCV, conv_b + (size_t)lay * EDD, uc);
        gemm_nt<<<gXp, 256>>>(uc, EDD,
                              x_proj + (size_t)lay * SPW * EDD, EDD,
                              sp, SPW, EDD, 0);
        gemm_nt<<<gDt, 256>>>(sp, SPW,
                              dt_w + (size_t)lay * EDD * DTR, DTR,
                              dtb, EDD, DTR, 0);
        dtact_kernel<<<(NTOK * EDD) / 256, 256>>>(dtb, dt_b + (size_t)lay * EDD);
        scan_kernel<<<(BB * EDD * 4) / 128, 128>>>(
            dtb, uc, sp, ug,
            A_log + (size_t)lay * EDD * NST, Dp + (size_t)lay * EDD, y);
        gemm_nt<<<gOut, 256>>>(y, EDD,
                               out_prj + (size_t)lay * DD * EDD, EDD,
                               h, DD, EDD, 1);
    }

    rmsnorm_kernel<<<NTOK, 256>>>(h, normf_w, xn);
    gemm_nt<<<gLog, 256>>>(xn, DD, emb, DD, out, VV, DD, 2);
}

// round 4
// speedup vs baseline: 2.6683x; 2.6683x over previous
#include <cuda_runtime.h>
#include <cuda_bf16.h>
#include <math.h>
#include <stdint.h>

// Problem dims
#define LL    512
#define BB    2
#define DD    768
#define EDD   1536
#define NST   16
#define KCV   4
#define DTR   48
#define VV    1024
#define NTOK  (LL*BB)   // 1024 tokens, t = b*LL + l
#define NLAY  24
#define SPW   80        // DT_RANK + 2*N

// ---------------------------------------------------------------------------
// Scratch (device globals; no allocation allowed). 256B-aligned for cp.async.
// ---------------------------------------------------------------------------
__device__ __align__(256) float g_h  [NTOK*DD];
__device__ __align__(256) float g_ug [NTOK*2*EDD];
__device__ __align__(256) float g_uc [NTOK*EDD];
__device__ __align__(256) float g_sp [NTOK*SPW];
__device__ __align__(256) float g_dtb[NTOK*EDD];

__device__ __align__(256) __nv_bfloat16 g_xnh[NTOK*DD],  g_xnl[NTOK*DD];
__device__ __align__(256) __nv_bfloat16 g_uch[NTOK*EDD], g_ucl[NTOK*EDD];
__device__ __align__(256) __nv_bfloat16 g_dth[NTOK*DTR], g_dtl[NTOK*DTR];
__device__ __align__(256) __nv_bfloat16 g_yh [NTOK*EDD], g_yl [NTOK*EDD];

// Converted weights (hi/lo bf16 split)
__device__ __align__(256) __nv_bfloat16 g_wih[NLAY*2*EDD*DD], g_wil[NLAY*2*EDD*DD];
__device__ __align__(256) __nv_bfloat16 g_wxh[NLAY*SPW*EDD],  g_wxl[NLAY*SPW*EDD];
__device__ __align__(256) __nv_bfloat16 g_wdh[NLAY*EDD*DTR],  g_wdl[NLAY*EDD*DTR];
__device__ __align__(256) __nv_bfloat16 g_woh[NLAY*DD*EDD],   g_wol[NLAY*DD*EDD];
__device__ __align__(256) __nv_bfloat16 g_weh[VV*DD],         g_wel[VV*DD];

// ---------------------------------------------------------------------------
// PTX helpers (arch-agnostic: cp.async / ldmatrix / mma.sync)
// ---------------------------------------------------------------------------
__device__ __forceinline__ uint32_t smem_u32(const void* p) {
    uint32_t a;
    asm("{ .reg .u64 t; cvta.to.shared.u64 t, %1; cvt.u32.u64 %0, t; }"
        : "=r"(a) : "l"(p));
    return a;
}

__device__ __forceinline__ void cp_async16(uint32_t dst, const void* src, uint32_t nbytes) {
    asm volatile("cp.async.cg.shared.global [%0], [%1], 16, %2;"
                 :: "r"(dst), "l"(src), "r"(nbytes) : "memory");
}
#define CP_COMMIT() asm volatile("cp.async.commit_group;" ::: "memory")
#define CP_WAIT1()  asm volatile("cp.async.wait_group 1;" ::: "memory")
#define CP_WAIT0()  asm volatile("cp.async.wait_group 0;" ::: "memory")

__device__ __forceinline__ void ldm_x4(uint32_t* r, uint32_t addr) {
    asm volatile("ldmatrix.sync.aligned.m8n8.x4.shared.b16 {%0,%1,%2,%3}, [%4];"
                 : "=r"(r[0]), "=r"(r[1]), "=r"(r[2]), "=r"(r[3]) : "r"(addr));
}

__device__ __forceinline__ void mma16816(float* d, const uint32_t* a, const uint32_t* b) {
    asm volatile(
        "mma.sync.aligned.m16n8k16.row.col.f32.bf16.bf16.f32 "
        "{%0,%1,%2,%3}, {%4,%5,%6,%7}, {%8,%9}, {%0,%1,%2,%3};"
        : "+f"(d[0]), "+f"(d[1]), "+f"(d[2]), "+f"(d[3])
        : "r"(a[0]), "r"(a[1]), "r"(a[2]), "r"(a[3]), "r"(b[0]), "r"(b[1]));
}

// ---------------------------------------------------------------------------
// mma.sync GEMM, bf16x3 compensated: C[M,N] = A[M,K] * W[N,K]^T (fp32-class)
// 128x128 CTA tile, K chunks of 32, 2-stage cp.async pipeline.
// Smem tile rows padded to 80B (40 bf16) -> conflict-free ldmatrix.
// mode 0: store; 1: +=; 2: logits permute.
// ---------------------------------------------------------------------------
#define TILE_B   10240            // 128 rows * 80B
#define BUF_B    (4*TILE_B)       // Ah, Al, Wh, Wl
#define GEMM_SMEM (2*BUF_B)       // 81920

__global__ void __launch_bounds__(256, 1) gemm_mma(
    const __nv_bfloat16* __restrict__ Ah, const __nv_bfloat16* __restrict__ Al, int lda,
    const __nv_bfloat16* __restrict__ Wh, const __nv_bfloat16* __restrict__ Wl, int ldw,
    float* __restrict__ C, int N, int K, int mode)
{
    extern __shared__ char smem[];
    const uint32_t sb = smem_u32(smem);
    const int tid  = threadIdx.x;
    const int lane = tid & 31;
    const int wid  = tid >> 5;
    const int wm   = wid & 3;        // 0..3  -> 32-row slice
    const int wn   = wid >> 2;       // 0..1  -> 64-col slice
    const int bm = blockIdx.y * 128;
    const int bn = blockIdx.x * 128;
    const int nc = (K + 31) >> 5;

    float acc[2][8][4];
#pragma unroll
    for (int i = 0; i < 2; i++)
#pragma unroll
        for (int j = 0; j < 8; j++)
#pragma unroll
            for (int k = 0; k < 4; k++) acc[i][j][k] = 0.f;

    // cp.async issue helper (inlined twice): 2048 16B ops / 256 thr = 8 per thr
    auto issue = [&](int c, int buf) {
        const int k0 = c << 5;
#pragma unroll
        for (int i = 0; i < 8; i++) {
            int linear = tid + (i << 8);
            int tile = linear >> 9;          // 0:Ah 1:Al 2:Wh 3:Wl
            int rem  = linear & 511;
            int row  = rem >> 2;
            int seg  = rem & 3;
            int kk   = k0 + (seg << 3);
            const __nv_bfloat16* src;
            int grow, ldk; bool rok;
            if (tile == 0)      { src = Ah; grow = bm + row; ldk = lda; rok = true; }
            else if (tile == 1) { src = Al; grow = bm + row; ldk = lda; rok = true; }
            else if (tile == 2) { src = Wh; grow = bn + row; ldk = ldw; rok = (bn + row) < N; }
            else                { src = Wl; grow = bn + row; ldk = ldw; rok = (bn + row) < N; }
            bool ok = rok && (kk < K);
            const void* gp = ok ? (const void*)(src + (size_t)grow * ldk + kk)
                                : (const void*)src;
            uint32_t dst = sb + buf * BUF_B + tile * TILE_B + row * 80 + seg * 16;
            cp_async16(dst, gp, ok ? 16u : 0u);
        }
    };

    issue(0, 0);
    CP_COMMIT();

    for (int c = 0; c < nc; c++) {
        const int buf = c & 1;
        if (c + 1 < nc) { issue(c + 1, buf ^ 1); CP_COMMIT(); CP_WAIT1(); }
        else            { CP_WAIT0(); }
        __syncthreads();

        const uint32_t bA = sb + buf * BUF_B;
        const uint32_t bW = bA + 2 * TILE_B;
        const int q = lane >> 3, l8 = lane & 7;

#pragma unroll
        for (int ks = 0; ks < 2; ks++) {
            const int k = ks << 4;
            // A fragments (hi, lo), 2 m-tiles each
            uint32_t ah[2][4], al_[2][4];
#pragma unroll
            for (int mt = 0; mt < 2; mt++) {
                uint32_t off = (uint32_t)((wm * 32 + mt * 16 + l8 + (q & 1) * 8) * 80
                                          + (k + (q >> 1) * 8) * 2);
                ldm_x4(ah[mt],  bA + off);
                ldm_x4(al_[mt], bA + TILE_B + off);
            }
            // B fragments (hi, lo), 4 n-tile pairs
            uint32_t bh[4][4], bl[4][4];
#pragma unroll
            for (int np = 0; np < 4; np++) {
                uint32_t off = (uint32_t)((wn * 64 + np * 16 + l8 + (q >> 1) * 8) * 80
                                          + (k + (q & 1) * 8) * 2);
                ldm_x4(bh[np], bW + off);
                ldm_x4(bl[np], bW + TILE_B + off);
            }
#pragma unroll
            for (int mt = 0; mt < 2; mt++)
#pragma unroll
                for (int np = 0; np < 4; np++) {
                    mma16816(acc[mt][2 * np],     ah[mt],  &bh[np][0]);
                    mma16816(acc[mt][2 * np + 1], ah[mt],  &bh[np][2]);
                    mma16816(acc[mt][2 * np],     ah[mt],  &bl[np][0]);
                    mma16816(acc[mt][2 * np + 1], ah[mt],  &bl[np][2]);
                    mma16816(acc[mt][2 * np],     al_[mt], &bh[np][0]);
                    mma16816(acc[mt][2 * np + 1], al_[mt], &bh[np][2]);
                }
        }
        __syncthreads();
    }

    // Epilogue
    const int tr = lane >> 2, tc = (lane & 3) * 2;
#pragma unroll
    for (int mt = 0; mt < 2; mt++) {
#pragma unroll
        for (int nt = 0; nt < 8; nt++) {
            float* a4 = acc[mt][nt];
            int r0 = bm + wm * 32 + mt * 16 + tr;
            int c0 = bn + wn * 64 + nt * 8 + tc;
#pragma unroll
            for (int half = 0; half < 2; half++) {
                int row = r0 + half * 8;
                float v0 = a4[half * 2], v1 = a4[half * 2 + 1];
                if (mode == 0) {
                    if (c0 < N)     C[(size_t)row * N + c0]     = v0;
                    if (c0 + 1 < N) C[(size_t)row * N + c0 + 1] = v1;
                } else if (mode == 1) {
                    if (c0 < N)     C[(size_t)row * N + c0]     += v0;
                    if (c0 + 1 < N) C[(size_t)row * N + c0 + 1] += v1;
                } else {
                    int lr = row & (LL - 1), br = row >> 9;
                    size_t base = (size_t)lr * (BB * VV) + (size_t)br * VV;
                    if (c0 < N)     C[base + c0]     = v0;
                    if (c0 + 1 < N) C[base + c0 + 1] = v1;
                }
            }
        }
    }
}

// ---------------------------------------------------------------------------
// Weight fp32 -> bf16 hi/lo conversion (grid-stride)
// ---------------------------------------------------------------------------
__global__ void wconv_kernel(const float* __restrict__ s,
                             __nv_bfloat16* __restrict__ h,
                             __nv_bfloat16* __restrict__ l, int n)
{
    for (int i = blockIdx.x * blockDim.x + threadIdx.x; i < n;
         i += gridDim.x * blockDim.x) {
        float v = s[i];
        __nv_bfloat16 hv = __float2bfloat16(v);
        h[i] = hv;
        l[i] = __float2bfloat16(v - __bfloat162float(hv));
    }
}

// dt_r slice of sp -> compact bf16 hi/lo [NTOK, 48]
__global__ void dtrconv_kernel(const float* __restrict__ sp,
                               __nv_bfloat16* __restrict__ h,
                               __nv_bfloat16* __restrict__ l)
{
    int t = blockIdx.x, j = threadIdx.x;   // 48 threads
    float v = sp[(size_t)t * SPW + j];
    __nv_bfloat16 hv = __float2bfloat16(v);
    h[(size_t)t * DTR + j] = hv;
    l[(size_t)t * DTR + j] = __float2bfloat16(v - __bfloat162float(hv));
}

// ---------------------------------------------------------------------------
// Embedding gather
// ---------------------------------------------------------------------------
__global__ void embed_kernel(const int* __restrict__ src,
                             const float* __restrict__ emb,
                             float* __restrict__ h)
{
    int t = blockIdx.x;
    int b = t >> 9, l = t & (LL - 1);
    int id = src[l * BB + b];
    const float* er = emb + (size_t)id * DD;
    float* hr = h + (size_t)t * DD;
    for (int i = threadIdx.x; i < DD; i += 256) hr[i] = er[i];
}

// ---------------------------------------------------------------------------
// RMSNorm -> bf16 hi/lo outputs
// ---------------------------------------------------------------------------
__global__ void rmsnorm2_kernel(const float* __restrict__ x,
                                const float* __restrict__ w,
                                __nv_bfloat16* __restrict__ oh,
                                __nv_bfloat16* __restrict__ ol)
{
    int t = blockIdx.x;
    const float* xr = x + (size_t)t * DD;
    float s = 0.f;
    for (int i = threadIdx.x; i < DD; i += 256) { float v = xr[i]; s += v * v; }
    __shared__ float red[256];
    red[threadIdx.x] = s;
    __syncthreads();
    for (int off = 128; off > 0; off >>= 1) {
        if (threadIdx.x < off) red[threadIdx.x] += red[threadIdx.x + off];
        __syncthreads();
    }
    float scale = rsqrtf(red[0] / (float)DD + 1e-5f);
    for (int i = threadIdx.x; i < DD; i += 256) {
        float v = xr[i] * scale * w[i];
        __nv_bfloat16 hv = __float2bfloat16(v);
        oh[(size_t)t * DD + i] = hv;
        ol[(size_t)t * DD + i] = __float2bfloat16(v - __bfloat162float(hv));
    }
}

// ---------------------------------------------------------------------------
// Depthwise causal conv (K=4) + SiLU; outputs fp32 (for scan) + bf16 hi/lo
// ---------------------------------------------------------------------------
__global__ void conv_silu_kernel(const float* __restrict__ ug,
                                 const float* __restrict__ cw,
                                 const float* __restrict__ cb,
                                 float* __restrict__ uc,
                                 __nv_bfloat16* __restrict__ uh,
                                 __nv_bfloat16* __restrict__ ul)
{
    int idx = blockIdx.x * blockDim.x + threadIdx.x;
    if (idx >= NTOK * EDD) return;
    int t = idx / EDD, e = idx - t * EDD;
    int l = t & (LL - 1);
    const float* base = ug + (size_t)t * (2 * EDD) + e;
    float4 w = *(const float4*)(cw + (size_t)e * KCV);
    float acc = cb[e];
    acc += (l >= 3 ? base[-3 * 2 * EDD] : 0.f) * w.x;
    acc += (l >= 2 ? base[-2 * 2 * EDD] : 0.f) * w.y;
    acc += (l >= 1 ? base[-1 * 2 * EDD] : 0.f) * w.z;
    acc += base[0] * w.w;
    float s = 1.f / (1.f + __expf(-acc));
    float v = acc * s;
    uc[idx] = v;
    __nv_bfloat16 hv = __float2bfloat16(v);
    uh[idx] = hv;
    ul[idx] = __float2bfloat16(v - __bfloat162float(hv));
}

// ---------------------------------------------------------------------------
// Selective scan: smem-staged 64-step windows, softplus fused, bf16 out.
// Block = 128 threads, 32 channels (e), 4 threads/channel (q = N-split).
// Grid = (ED/32, B).
// ---------------------------------------------------------------------------
__global__ void __launch_bounds__(128) scan2_kernel(
    const float* __restrict__ dtraw,   // [NTOK, ED] pre-activation
    const float* __restrict__ dtbias,  // [ED]
    const float* __restrict__ uc,      // [NTOK, ED]
    const float* __restrict__ sp,      // [NTOK, 80]
    const float* __restrict__ ug,      // [NTOK, 2ED] (gate at +ED)
    const float* __restrict__ A_log,   // [ED, 16]
    const float* __restrict__ Dp,      // [ED]
    __nv_bfloat16* __restrict__ yh,
    __nv_bfloat16* __restrict__ yl)
{
    __shared__ float  sdt[64][32], suc[64][32], sg[64][32];
    __shared__ float4 sB[64][4], sC[64][4];

    const int b  = blockIdx.y;
    const int eb = blockIdx.x * 32;
    const int tid = threadIdx.x;
    const int q = tid & 3, er = tid >> 2;
    const int e = eb + er;

    float4 al = *(const float4*)(A_log + (size_t)e * NST + q * 4);
    float a0 = -__expf(al.x), a1 = -__expf(al.y),
          a2 = -__expf(al.z), a3 = -__expf(al.w);
    const float dD  = Dp[e];
    const float bsv = dtbias[e];

    float h0 = 0.f, h1 = 0.f, h2 = 0.f, h3 = 0.f;

    for (int w = 0; w < 8; w++) {
        const int t0 = b * LL + w * 64;
#pragma unroll
        for (int i = 0; i < 16; i++) {
            int idx = tid + i * 128;
            int s = idx >> 5, j = idx & 31;
            size_t tr = (size_t)(t0 + s);
            sdt[s][j] = dtraw[tr * EDD + eb + j];
            suc[s][j] = uc  [tr * EDD + eb + j];
            sg [s][j] = ug  [tr * (2 * EDD) + EDD + eb + j];
            float v = sp[tr * SPW + DTR + j];
            if (j < 16) ((float*)&sB[s][0])[j]      = v;
            else        ((float*)&sC[s][0])[j - 16] = v;
        }
        __syncthreads();
#pragma unroll 4
        for (int s = 0; s < 64; s++) {
            float x = sdt[s][er] + bsv;
            float dtv = (x > 15.f) ? x : log1pf(__expf(x));
            float u = suc[s][er];
            float4 Bv = sB[s][q], Cv = sC[s][q];
            float du = dtv * u;
            h0 = __expf(dtv * a0) * h0 + du * Bv.x;
            h1 = __expf(dtv * a1) * h1 + du * Bv.y;
            h2 = __expf(dtv * a2) * h2 + du * Bv.z;
            h3 = __expf(dtv * a3) * h3 + du * Bv.w;
            float ys = h0 * Cv.x + h1 * Cv.y + h2 * Cv.z + h3 * Cv.w;
            ys += __shfl_xor_sync(0xffffffffu, ys, 1);
            ys += __shfl_xor_sync(0xffffffffu, ys, 2);
            if (q == 0) {
                float gv = sg[s][er];
                float yv = (ys + u * dD) * (gv / (1.f + __expf(-gv)));
                __nv_bfloat16 hv = __float2bfloat16(yv);
                size_t o = (size_t)(t0 + s) * EDD + e;
                yh[o] = hv;
                yl[o] = __float2bfloat16(yv - __bfloat162float(hv));
            }
        }
        __syncthreads();
    }
}

// ---------------------------------------------------------------------------
extern "C" void kernel_launch(void* const* d_in, const int* in_sizes, int n_in,
                              void* d_out, int out_size)
{
    const int*   src     = (const int*)  d_in[0];
    const float* emb     = (const float*)d_in[1];
    const float* norm_w  = (const float*)d_in[2];
    const float* in_proj = (const float*)d_in[3];
    const float* conv_w  = (const float*)d_in[4];
    const float* conv_b  = (const float*)d_in[5];
    const float* x_proj  = (const float*)d_in[6];
    const float* dt_w    = (const float*)d_in[7];
    const float* dt_b    = (const float*)d_in[8];
    const float* A_log   = (const float*)d_in[9];
    const float* Dp      = (const float*)d_in[10];
    const float* out_prj = (const float*)d_in[11];
    const float* normf_w = (const float*)d_in[12];
    float* out = (float*)d_out;
    (void)in_sizes; (void)n_in; (void)out_size;

    cudaFuncSetAttribute(gemm_mma,
                         cudaFuncAttributeMaxDynamicSharedMemorySize, GEMM_SMEM);

    float *h, *ug, *uc, *sp, *dtb;
    __nv_bfloat16 *xnh, *xnl, *uch, *ucl, *dth, *dtl, *yh, *yl;
    __nv_bfloat16 *wih, *wil, *wxh, *wxl, *wdh, *wdl, *woh, *wol, *weh, *wel;
    cudaGetSymbolAddress((void**)&h,   g_h);
    cudaGetSymbolAddress((void**)&ug,  g_ug);
    cudaGetSymbolAddress((void**)&uc,  g_uc);
    cudaGetSymbolAddress((void**)&sp,  g_sp);
    cudaGetSymbolAddress((void**)&dtb, g_dtb);
    cudaGetSymbolAddress((void**)&xnh, g_xnh);
    cudaGetSymbolAddress((void**)&xnl, g_xnl);
    cudaGetSymbolAddress((void**)&uch, g_uch);
    cudaGetSymbolAddress((void**)&ucl, g_ucl);
    cudaGetSymbolAddress((void**)&dth, g_dth);
    cudaGetSymbolAddress((void**)&dtl, g_dtl);
    cudaGetSymbolAddress((void**)&yh,  g_yh);
    cudaGetSymbolAddress((void**)&yl,  g_yl);
    cudaGetSymbolAddress((void**)&wih, g_wih);
    cudaGetSymbolAddress((void**)&wil, g_wil);
    cudaGetSymbolAddress((void**)&wxh, g_wxh);
    cudaGetSymbolAddress((void**)&wxl, g_wxl);
    cudaGetSymbolAddress((void**)&wdh, g_wdh);
    cudaGetSymbolAddress((void**)&wdl, g_wdl);
    cudaGetSymbolAddress((void**)&woh, g_woh);
    cudaGetSymbolAddress((void**)&wol, g_wol);
    cudaGetSymbolAddress((void**)&weh, g_weh);
    cudaGetSymbolAddress((void**)&wel, g_wel);

    // Weight conversions (once per launch)
    wconv_kernel<<<2048, 256>>>(in_proj, wih, wil, NLAY * 2 * EDD * DD);
    wconv_kernel<<<2048, 256>>>(x_proj,  wxh, wxl, NLAY * SPW * EDD);
    wconv_kernel<<<1024, 256>>>(dt_w,    wdh, wdl, NLAY * EDD * DTR);
    wconv_kernel<<<2048, 256>>>(out_prj, woh, wol, NLAY * DD * EDD);
    wconv_kernel<<<1024, 256>>>(emb,     weh, wel, VV * DD);

    embed_kernel<<<NTOK, 256>>>(src, emb, h);

    const dim3 gIn (2 * EDD / 128, NTOK / 128);   // N=3072
    const dim3 gXp (1,             NTOK / 128);   // N=80 (padded to 128)
    const dim3 gDt (EDD / 128,     NTOK / 128);   // N=1536
    const dim3 gOut(DD / 128,      NTOK / 128);   // N=768
    const dim3 gLog(VV / 128,      NTOK / 128);   // N=1024
    const dim3 gScan(EDD / 32, BB);

    for (int lay = 0; lay < NLAY; lay++) {
        rmsnorm2_kernel<<<NTOK, 256>>>(h, norm_w + (size_t)lay * DD, xnh, xnl);
        gemm_mma<<<gIn, 256, GEMM_SMEM>>>(
            xnh, xnl, DD,
            wih + (size_t)lay * 2 * EDD * DD, wil + (size_t)lay * 2 * EDD * DD, DD,
            ug, 2 * EDD, DD, 0);
        conv_silu_kernel<<<(NTOK * EDD) / 256, 256>>>(
            ug, conv_w + (size_t)lay * EDD * KCV, conv_b + (size_t)lay * EDD,
            uc, uch, ucl);
        gemm_mma<<<gXp, 256, GEMM_SMEM>>>(
            uch, ucl, EDD,
            wxh + (size_t)lay * SPW * EDD, wxl + (size_t)lay * SPW * EDD, EDD,
            sp, SPW, EDD, 0);
        dtrconv_kernel<<<NTOK, DTR>>>(sp, dth, dtl);
        gemm_mma<<<gDt, 256, GEMM_SMEM>>>(
            dth, dtl, DTR,
            wdh + (size_t)lay * EDD * DTR, wdl + (size_t)lay * EDD * DTR, DTR,
            dtb, EDD, DTR, 0);
        scan2_kernel<<<gScan, 128>>>(
            dtb, dt_b + (size_t)lay * EDD, uc, sp, ug,
            A_log + (size_t)lay * EDD * NST, Dp + (size_t)lay * EDD, yh, yl);
        gemm_mma<<<gOut, 256, GEMM_SMEM>>>(
            yh, yl, EDD,
            woh + (size_t)lay * DD * EDD, wol + (size_t)lay * DD * EDD, EDD,
            h, DD, EDD, 1);
    }

    rmsnorm2_kernel<<<NTOK, 256>>>(h, normf_w, xnh, xnl);
    gemm_mma<<<gLog, 256, GEMM_SMEM>>>(
        xnh, xnl, DD, weh, wel, DD, out, VV, DD, 2);
}

// round 6
// speedup vs baseline: 3.8165x; 1.4303x over previous
#include <cuda_runtime.h>
#include <cuda_bf16.h>
#include <math.h>
#include <stdint.h>

// Problem dims
#define LL    512
#define BB    2
#define DD    768
#define EDD   1536
#define NST   16
#define KCV   4
#define DTR   48
#define VV    1024
#define NTOK  (LL*BB)   // 1024 tokens, t = b*LL + l
#define NLAY  24
#define SPW   80        // DT_RANK + 2*N

// ---------------------------------------------------------------------------
// Scratch (device globals; no allocation allowed). 256B-aligned for cp.async.
// ---------------------------------------------------------------------------
__device__ __align__(256) float g_h  [NTOK*DD];
__device__ __align__(256) float g_ug [NTOK*2*EDD];
__device__ __align__(256) float g_sp [NTOK*SPW];
__device__ __align__(256) float g_dtb[NTOK*EDD];
__device__ __align__(256) float g_part[3*NTOK*2*EDD];   // split-K partials (max 3x1024x3072)

__device__ __align__(256) __nv_bfloat16 g_xnh[NTOK*DD],  g_xnl[NTOK*DD];
__device__ __align__(256) __nv_bfloat16 g_uch[NTOK*EDD], g_ucl[NTOK*EDD];
__device__ __align__(256) __nv_bfloat16 g_dth[NTOK*DTR], g_dtl[NTOK*DTR];
__device__ __align__(256) __nv_bfloat16 g_yh [NTOK*EDD], g_yl [NTOK*EDD];

// Converted weights (hi/lo bf16 split)
__device__ __align__(256) __nv_bfloat16 g_wih[NLAY*2*EDD*DD], g_wil[NLAY*2*EDD*DD];
__device__ __align__(256) __nv_bfloat16 g_wxh[NLAY*SPW*EDD],  g_wxl[NLAY*SPW*EDD];
__device__ __align__(256) __nv_bfloat16 g_wdh[NLAY*EDD*DTR],  g_wdl[NLAY*EDD*DTR];
__device__ __align__(256) __nv_bfloat16 g_woh[NLAY*DD*EDD],   g_wol[NLAY*DD*EDD];
__device__ __align__(256) __nv_bfloat16 g_weh[VV*DD],         g_wel[VV*DD];

// ---------------------------------------------------------------------------
// PTX helpers (arch-agnostic: cp.async / ldmatrix / mma.sync)
// ---------------------------------------------------------------------------
__device__ __forceinline__ uint32_t smem_u32(const void* p) {
    uint32_t a;
    asm("{ .reg .u64 t; cvta.to.shared.u64 t, %1; cvt.u32.u64 %0, t; }"
        : "=r"(a) : "l"(p));
    return a;
}

__device__ __forceinline__ void cp_async16(uint32_t dst, const void* src, uint32_t nbytes) {
    asm volatile("cp.async.cg.shared.global [%0], [%1], 16, %2;"
                 :: "r"(dst), "l"(src), "r"(nbytes) : "memory");
}
#define CP_COMMIT() asm volatile("cp.async.commit_group;" ::: "memory")
#define CP_WAIT2()  asm volatile("cp.async.wait_group 2;" ::: "memory")
#define CP_WAIT1()  asm volatile("cp.async.wait_group 1;" ::: "memory")
#define CP_WAIT0()  asm volatile("cp.async.wait_group 0;" ::: "memory")

__device__ __forceinline__ void ldm_x4(uint32_t* r, uint32_t addr) {
    asm volatile("ldmatrix.sync.aligned.m8n8.x4.shared.b16 {%0,%1,%2,%3}, [%4];"
                 : "=r"(r[0]), "=r"(r[1]), "=r"(r[2]), "=r"(r[3]) : "r"(addr));
}

__device__ __forceinline__ void mma16816(float* d, const uint32_t* a, const uint32_t* b) {
    asm volatile(
        "mma.sync.aligned.m16n8k16.row.col.f32.bf16.bf16.f32 "
        "{%0,%1,%2,%3}, {%4,%5,%6,%7}, {%8,%9}, {%0,%1,%2,%3};"
        : "+f"(d[0]), "+f"(d[1]), "+f"(d[2]), "+f"(d[3])
        : "r"(a[0]), "r"(a[1]), "r"(a[2]), "r"(a[3]), "r"(b[0]), "r"(b[1]));
}

// ---------------------------------------------------------------------------
// mma.sync GEMM, bf16x3 compensated: C[M,N] = A[M,K] * W[N,K]^T (fp32-class)
// 128x128 CTA tile, K chunks of 32, 3-stage cp.async pipeline, split-K via
// blockIdx.z (each split covers klen of K; partials stored at z*1024*N).
// Smem rows padded to 80B -> conflict-free ldmatrix.
// mode 0: store; 1: +=; 2: logits permute; 3: partial store (split-K).
// ---------------------------------------------------------------------------
#define TILE_B   10240            // 128 rows * 80B
#define BUF_B    (4*TILE_B)       // Ah, Al, Wh, Wl
#define GEMM_SMEM (3*BUF_B)       // 3 stages = 122880

__global__ void __launch_bounds__(256, 1) gemm_mma(
    const __nv_bfloat16* __restrict__ Ah, const __nv_bfloat16* __restrict__ Al, int lda,
    const __nv_bfloat16* __restrict__ Wh, const __nv_bfloat16* __restrict__ Wl, int ldw,
    float* __restrict__ C, int N, int K, int mode, int klen)
{
    extern __shared__ char smem[];
    const uint32_t sb = smem_u32(smem);
    const int tid  = threadIdx.x;
    const int lane = tid & 31;
    const int wid  = tid >> 5;
    const int wm   = wid & 3;        // 0..3  -> 32-row slice
    const int wn   = wid >> 2;       // 0..1  -> 64-col slice
    const int bm = blockIdx.y * 128;
    const int bn = blockIdx.x * 128;
    const int koff = blockIdx.z * klen;
    const int kend = min(koff + klen, K);
    const int nc = (kend - koff + 31) >> 5;
    if (mode == 3) C += (size_t)blockIdx.z * NTOK * N;

    float acc[2][8][4];
#pragma unroll
    for (int i = 0; i < 2; i++)
#pragma unroll
        for (int j = 0; j < 8; j++)
#pragma unroll
            for (int k = 0; k < 4; k++) acc[i][j][k] = 0.f;

    // Chunk-invariant load precompute: 8 cp.async per thread per chunk.
    // i: 0,1 -> Ah rows r0/r0+64 ; 2,3 -> Al ; 4,5 -> Wh ; 6,7 -> Wl
    const int seg = tid & 3;              // 16B segment within 64-elem row chunk
    const int r0  = tid >> 2;             // 0..63
    const __nv_bfloat16* gsrc[8];
    uint32_t dsto[8];
    bool rowok[8];
#pragma unroll
    for (int i = 0; i < 8; i++) {
        const int tile = i >> 1;
        const int row  = (i & 1) * 64 + r0;
        const __nv_bfloat16* s; int gr, ld; bool rk;
        if (tile == 0)      { s = Ah; gr = bm + row; ld = lda; rk = true; }
        else if (tile == 1) { s = Al; gr = bm + row; ld = lda; rk = true; }
        else if (tile == 2) { s = Wh; gr = bn + row; ld = ldw; rk = (bn + row) < N; }
        else                { s = Wl; gr = bn + row; ld = ldw; rk = (bn + row) < N; }
        gsrc[i]  = s + (size_t)gr * ld + koff + seg * 8;
        dsto[i]  = (uint32_t)(tile * TILE_B + row * 80 + seg * 16);
        rowok[i] = rk;
    }
    const int kseg0 = koff + seg * 8;

    auto issue = [&](int c, int buf) {
        const int kk = kseg0 + (c << 5);
        const bool kok = kk < kend;
        const uint32_t base = sb + buf * BUF_B;
#pragma unroll
        for (int i = 0; i < 8; i++) {
            bool ok = rowok[i] && kok;
            cp_async16(base + dsto[i],
                       ok ? (const void*)(gsrc[i] + (c << 5)) : (const void*)Ah,
                       ok ? 16u : 0u);
        }
    };

    issue(0, 0); CP_COMMIT();
    if (nc > 1) { issue(1, 1); CP_COMMIT(); }

    for (int c = 0; c < nc; c++) {
        const int buf = c % 3;
        if (c + 2 < nc) { issue(c + 2, (c + 2) % 3); CP_COMMIT(); CP_WAIT2(); }
        else if (c + 1 < nc) { CP_WAIT1(); }
        else { CP_WAIT0(); }
        __syncthreads();

        const uint32_t bA = sb + buf * BUF_B;
        const uint32_t bW = bA + 2 * TILE_B;
        const int q = lane >> 3, l8 = lane & 7;

#pragma unroll
        for (int ks = 0; ks < 2; ks++) {
            const int k = ks << 4;
            uint32_t ah[2][4], al_[2][4];
#pragma unroll
            for (int mt = 0; mt < 2; mt++) {
                uint32_t off = (uint32_t)((wm * 32 + mt * 16 + l8 + (q & 1) * 8) * 80
                                          + (k + (q >> 1) * 8) * 2);
                ldm_x4(ah[mt],  bA + off);
                ldm_x4(al_[mt], bA + TILE_B + off);
            }
            uint32_t bh[4][4], bl[4][4];
#pragma unroll
            for (int np = 0; np < 4; np++) {
                uint32_t off = (uint32_t)((wn * 64 + np * 16 + l8 + (q >> 1) * 8) * 80
                                          + (k + (q & 1) * 8) * 2);
                ldm_x4(bh[np], bW + off);
                ldm_x4(bl[np], bW + TILE_B + off);
            }
#pragma unroll
            for (int mt = 0; mt < 2; mt++)
#pragma unroll
                for (int np = 0; np < 4; np++) {
                    mma16816(acc[mt][2 * np],     ah[mt],  &bh[np][0]);
                    mma16816(acc[mt][2 * np + 1], ah[mt],  &bh[np][2]);
                    mma16816(acc[mt][2 * np],     ah[mt],  &bl[np][0]);
                    mma16816(acc[mt][2 * np + 1], ah[mt],  &bl[np][2]);
                    mma16816(acc[mt][2 * np],     al_[mt], &bh[np][0]);
                    mma16816(acc[mt][2 * np + 1], al_[mt], &bh[np][2]);
                }
        }
        __syncthreads();
    }

    // Epilogue
    const int tr = lane >> 2, tc = (lane & 3) * 2;
#pragma unroll
    for (int mt = 0; mt < 2; mt++) {
#pragma unroll
        for (int nt = 0; nt < 8; nt++) {
            float* a4 = acc[mt][nt];
            int r0e = bm + wm * 32 + mt * 16 + tr;
            int c0 = bn + wn * 64 + nt * 8 + tc;
#pragma unroll
            for (int half = 0; half < 2; half++) {
                int row = r0e + half * 8;
                float v0 = a4[half * 2], v1 = a4[half * 2 + 1];
                if (mode == 1) {
                    if (c0 < N)     C[(size_t)row * N + c0]     += v0;
                    if (c0 + 1 < N) C[(size_t)row * N + c0 + 1] += v1;
                } else if (mode == 2) {
                    int lr = row & (LL - 1), br = row >> 9;
                    size_t base = (size_t)lr * (BB * VV) + (size_t)br * VV;
                    if (c0 < N)     C[base + c0]     = v0;
                    if (c0 + 1 < N) C[base + c0 + 1] = v1;
                } else {
                    if (c0 < N)     C[(size_t)row * N + c0]     = v0;
                    if (c0 + 1 < N) C[(size_t)row * N + c0 + 1] = v1;
                }
            }
        }
    }
}

// ---------------------------------------------------------------------------
// Split-K reduce: dst = sum of ns partials. mode 0: store; 1: +=;
// 2: logits permute ([t][v] -> out[l][b][v]). float4-vectorized.
// ---------------------------------------------------------------------------
__global__ void reduce_kernel(float* __restrict__ dst,
                              const float* __restrict__ part,
                              int n4, int stride4, int ns, int mode)
{
    int i = blockIdx.x * blockDim.x + threadIdx.x;
    if (i >= n4) return;
    const float4* p4 = (const float4*)part;
    float4 s = p4[i];
    for (int k = 1; k < ns; k++) {
        float4 v = p4[i + (size_t)k * stride4];
        s.x += v.x; s.y += v.y; s.z += v.z; s.w += v.w;
    }
    if (mode == 0) {
        ((float4*)dst)[i] = s;
    } else if (mode == 1) {
        float4 d = ((float4*)dst)[i];
        d.x += s.x; d.y += s.y; d.z += s.z; d.w += s.w;
        ((float4*)dst)[i] = d;
    } else {
        int idx = i << 2;
        int t = idx >> 10, v = idx & (VV - 1);
        int l = t & (LL - 1), b = t >> 9;
        ((float4*)(dst + (size_t)l * (BB * VV) + (size_t)b * VV + v))[0] = s;
    }
}

// xp reduce: sp[1024][80] = sum of 16 partials; also emit dt_r bf16 hi/lo.
__global__ void reduce_xp_kernel(float* __restrict__ sp,
                                 const float* __restrict__ part,
                                 __nv_bfloat16* __restrict__ dth,
                                 __nv_bfloat16* __restrict__ dtl)
{
    int i = blockIdx.x * blockDim.x + threadIdx.x;
    if (i >= NTOK * SPW) return;
    float s = part[i];
#pragma unroll
    for (int k = 1; k < 16; k++) s += part[i + k * (NTOK * SPW)];
    sp[i] = s;
    int col = i % SPW;
    if (col < DTR) {
        int t = i / SPW;
        __nv_bfloat16 hv = __float2bfloat16(s);
        dth[(size_t)t * DTR + col] = hv;
        dtl[(size_t)t * DTR + col] = __float2bfloat16(s - __bfloat162float(hv));
    }
}

// ---------------------------------------------------------------------------
// Weight fp32 -> bf16 hi/lo conversion (vectorized)
// ---------------------------------------------------------------------------
__global__ void wconv_kernel(const float4* __restrict__ s,
                             __nv_bfloat162* __restrict__ h,
                             __nv_bfloat162* __restrict__ l, int n4)
{
    for (int i = blockIdx.x * blockDim.x + threadIdx.x; i < n4;
         i += gridDim.x * blockDim.x) {
        float4 v = s[i];
        __nv_bfloat16 h0 = __float2bfloat16(v.x), h1 = __float2bfloat16(v.y);
        __nv_bfloat16 h2 = __float2bfloat16(v.z), h3 = __float2bfloat16(v.w);
        h[2 * i]     = __nv_bfloat162(h0, h1);
        h[2 * i + 1] = __nv_bfloat162(h2, h3);
        l[2 * i]     = __nv_bfloat162(
            __float2bfloat16(v.x - __bfloat162float(h0)),
            __float2bfloat16(v.y - __bfloat162float(h1)));
        l[2 * i + 1] = __nv_bfloat162(
            __float2bfloat16(v.z - __bfloat162float(h2)),
            __float2bfloat16(v.w - __bfloat162float(h3)));
    }
}

// ---------------------------------------------------------------------------
// Embedding gather
// ---------------------------------------------------------------------------
__global__ void embed_kernel(const int* __restrict__ src,
                             const float* __restrict__ emb,
                             float* __restrict__ h)
{
    int t = blockIdx.x;
    int b = t >> 9, l = t & (LL - 1);
    int id = src[l * BB + b];
    const float* er = emb + (size_t)id * DD;
    float* hr = h + (size_t)t * DD;
    for (int i = threadIdx.x; i < DD; i += 256) hr[i] = er[i];
}

// ---------------------------------------------------------------------------
// RMSNorm -> bf16 hi/lo outputs
// ---------------------------------------------------------------------------
__global__ void rmsnorm2_kernel(const float* __restrict__ x,
                                const float* __restrict__ w,
                                __nv_bfloat16* __restrict__ oh,
                                __nv_bfloat16* __restrict__ ol)
{
    int t = blockIdx.x;
    const float* xr = x + (size_t)t * DD;
    float s = 0.f;
    for (int i = threadIdx.x; i < DD; i += 256) { float v = xr[i]; s += v * v; }
    __shared__ float red[256];
    red[threadIdx.x] = s;
    __syncthreads();
    for (int off = 128; off > 0; off >>= 1) {
        if (threadIdx.x < off) red[threadIdx.x] += red[threadIdx.x + off];
        __syncthreads();
    }
    float scale = rsqrtf(red[0] / (float)DD + 1e-5f);
    for (int i = threadIdx.x; i < DD; i += 256) {
        float v = xr[i] * scale * w[i];
        __nv_bfloat16 hv = __float2bfloat16(v);
        oh[(size_t)t * DD + i] = hv;
        ol[(size_t)t * DD + i] = __float2bfloat16(v - __bfloat162float(hv));
    }
}

// ---------------------------------------------------------------------------
// Depthwise causal conv (K=4) + SiLU -> bf16 hi/lo
// ---------------------------------------------------------------------------
__global__ void conv_silu_kernel(const float* __restrict__ ug,
                                 const float* __restrict__ cw,
                                 const float* __restrict__ cb,
                                 __nv_bfloat16* __restrict__ uh,
                                 __nv_bfloat16* __restrict__ ul)
{
    int idx = blockIdx.x * blockDim.x + threadIdx.x;
    if (idx >= NTOK * EDD) return;
    int t = idx / EDD, e = idx - t * EDD;
    int l = t & (LL - 1);
    const float* base = ug + (size_t)t * (2 * EDD) + e;
    float4 w = *(const float4*)(cw + (size_t)e * KCV);
    float acc = cb[e];
    acc += (l >= 3 ? base[-3 * 2 * EDD] : 0.f) * w.x;
    acc += (l >= 2 ? base[-2 * 2 * EDD] : 0.f) * w.y;
    acc += (l >= 1 ? base[-1 * 2 * EDD] : 0.f) * w.z;
    acc += base[0] * w.w;
    float s = 1.f / (1.f + __expf(-acc));
    float v = acc * s;
    __nv_bfloat16 hv = __float2bfloat16(v);
    uh[idx] = hv;
    ul[idx] = __float2bfloat16(v - __bfloat162float(hv));
}

// ---------------------------------------------------------------------------
// Selective scan: smem-staged 64-step windows, softplus fused, bf16 out.
// Block = 128 threads, 32 channels (e), 4 threads/channel (q = N-split).
// ---------------------------------------------------------------------------
__global__ void __launch_bounds__(128) scan2_kernel(
    const float* __restrict__ dtraw,
    const float* __restrict__ dtbias,
    const __nv_bfloat16* __restrict__ uch,
    const __nv_bfloat16* __restrict__ ucl,
    const float* __restrict__ sp,
    const float* __restrict__ ug,
    const float* __restrict__ A_log,
    const float* __restrict__ Dp,
    __nv_bfloat16* __restrict__ yh,
    __nv_bfloat16* __restrict__ yl)
{
    __shared__ float  sdt[64][32], suc[64][32], sg[64][32];
    __shared__ float4 sB[64][4], sC[64][4];

    const int b  = blockIdx.y;
    const int eb = blockIdx.x * 32;
    const int tid = threadIdx.x;
    const int q = tid & 3, er = tid >> 2;
    const int e = eb + er;

    float4 al = *(const float4*)(A_log + (size_t)e * NST + q * 4);
    float a0 = -__expf(al.x), a1 = -__expf(al.y),
          a2 = -__expf(al.z), a3 = -__expf(al.w);
    const float dD  = Dp[e];
    const float bsv = dtbias[e];

    float h0 = 0.f, h1 = 0.f, h2 = 0.f, h3 = 0.f;

    for (int w = 0; w < 8; w++) {
        const int t0 = b * LL + w * 64;
#pragma unroll
        for (int i = 0; i < 16; i++) {
            int idx = tid + i * 128;
            int s = idx >> 5, j = idx & 31;
            size_t tr = (size_t)(t0 + s);
            sdt[s][j] = dtraw[tr * EDD + eb + j];
            suc[s][j] = __bfloat162float(uch[tr * EDD + eb + j])
                      + __bfloat162float(ucl[tr * EDD + eb + j]);
            sg [s][j] = ug[tr * (2 * EDD) + EDD + eb + j];
            float v = sp[tr * SPW + DTR + j];
            if (j < 16) ((float*)&sB[s][0])[j]      = v;
            else        ((float*)&sC[s][0])[j - 16] = v;
        }
        __syncthreads();
#pragma unroll 4
        for (int s = 0; s < 64; s++) {
            float x = sdt[s][er] + bsv;
            float dtv = (x > 15.f) ? x : log1pf(__expf(x));
            float u = suc[s][er];
            float4 Bv = sB[s][q], Cv = sC[s][q];
            float du = dtv * u;
            h0 = __expf(dtv * a0) * h0 + du * Bv.x;
            h1 = __expf(dtv * a1) * h1 + du * Bv.y;
            h2 = __expf(dtv * a2) * h2 + du * Bv.z;
            h3 = __expf(dtv * a3) * h3 + du * Bv.w;
            float ys = h0 * Cv.x + h1 * Cv.y + h2 * Cv.z + h3 * Cv.w;
            ys += __shfl_xor_sync(0xffffffffu, ys, 1);
            ys += __shfl_xor_sync(0xffffffffu, ys, 2);
            if (q == 0) {
                float gv = sg[s][er];
                float yv = (ys + u * dD) * (gv / (1.f + __expf(-gv)));
                __nv_bfloat16 hv = __float2bfloat16(yv);
                size_t o = (size_t)(t0 + s) * EDD + e;
                yh[o] = hv;
                yl[o] = __float2bfloat16(yv - __bfloat162float(hv));
            }
        }
        __syncthreads();
    }
}

// ---------------------------------------------------------------------------
extern "C" void kernel_launch(void* const* d_in, const int* in_sizes, int n_in,
                              void* d_out, int out_size)
{
    const int*   src     = (const int*)  d_in[0];
    const float* emb     = (const float*)d_in[1];
    const float* norm_w  = (const float*)d_in[2];
    const float* in_proj = (const float*)d_in[3];
    const float* conv_w  = (const float*)d_in[4];
    const float* conv_b  = (const float*)d_in[5];
    const float* x_proj  = (const float*)d_in[6];
    const float* dt_w    = (const float*)d_in[7];
    const float* dt_b    = (const float*)d_in[8];
    const float* A_log   = (const float*)d_in[9];
    const float* Dp      = (const float*)d_in[10];
    const float* out_prj = (const float*)d_in[11];
    const float* normf_w = (const float*)d_in[12];
    float* out = (float*)d_out;
    (void)in_sizes; (void)n_in; (void)out_size;

    cudaFuncSetAttribute(gemm_mma,
                         cudaFuncAttributeMaxDynamicSharedMemorySize, GEMM_SMEM);

    float *h, *ug, *sp, *dtb, *part;
    __nv_bfloat16 *xnh, *xnl, *uch, *ucl, *dth, *dtl, *yh, *yl;
    __nv_bfloat16 *wih, *wil, *wxh, *wxl, *wdh, *wdl, *woh, *wol, *weh, *wel;
    cudaGetSymbolAddress((void**)&h,    g_h);
    cudaGetSymbolAddress((void**)&ug,   g_ug);
    cudaGetSymbolAddress((void**)&sp,   g_sp);
    cudaGetSymbolAddress((void**)&dtb,  g_dtb);
    cudaGetSymbolAddress((void**)&part, g_part);
    cudaGetSymbolAddress((void**)&xnh, g_xnh);
    cudaGetSymbolAddress((void**)&xnl, g_xnl);
    cudaGetSymbolAddress((void**)&uch, g_uch);
    cudaGetSymbolAddress((void**)&ucl, g_ucl);
    cudaGetSymbolAddress((void**)&dth, g_dth);
    cudaGetSymbolAddress((void**)&dtl, g_dtl);
    cudaGetSymbolAddress((void**)&yh,  g_yh);
    cudaGetSymbolAddress((void**)&yl,  g_yl);
    cudaGetSymbolAddress((void**)&wih, g_wih);
    cudaGetSymbolAddress((void**)&wil, g_wil);
    cudaGetSymbolAddress((void**)&wxh, g_wxh);
    cudaGetSymbolAddress((void**)&wxl, g_wxl);
    cudaGetSymbolAddress((void**)&wdh, g_wdh);
    cudaGetSymbolAddress((void**)&wdl, g_wdl);
    cudaGetSymbolAddress((void**)&woh, g_woh);
    cudaGetSymbolAddress((void**)&wol, g_wol);
    cudaGetSymbolAddress((void**)&weh, g_weh);
    cudaGetSymbolAddress((void**)&wel, g_wel);

    // Launch order chosen so launch #6 (ncu -s 5 -c 1) is the in_proj GEMM.
    embed_kernel<<<NTOK, 256>>>(src, emb, h);                                   // 1
    wconv_kernel<<<2048, 256>>>((const float4*)in_proj,
        (__nv_bfloat162*)wih, (__nv_bfloat162*)wil, NLAY * 2 * EDD * DD / 4);   // 2
    wconv_kernel<<<1024, 256>>>((const float4*)x_proj,
        (__nv_bfloat162*)wxh, (__nv_bfloat162*)wxl, NLAY * SPW * EDD / 4);      // 3
    wconv_kernel<<<1024, 256>>>((const float4*)dt_w,
        (__nv_bfloat162*)wdh, (__nv_bfloat162*)wdl, NLAY * EDD * DTR / 4);      // 4

    const dim3 gIn (2 * EDD / 128, NTOK / 128, 3);   // N=3072, klen 256
    const dim3 gXp (1,             NTOK / 128, 16);  // N=80,   klen 96
    const dim3 gDt (EDD / 128,     NTOK / 128, 1);   // N=1536, K=48
    const dim3 gOut(DD / 128,      NTOK / 128, 3);   // N=768,  klen 512
    const dim3 gLog(VV / 128,      NTOK / 128, 2);   // N=1024, klen 384
    const dim3 gScan(EDD / 32, BB);

    for (int lay = 0; lay < NLAY; lay++) {
        rmsnorm2_kernel<<<NTOK, 256>>>(h, norm_w + (size_t)lay * DD, xnh, xnl); // 5
        gemm_mma<<<gIn, 256, GEMM_SMEM>>>(                                      // 6 <- profiled
            xnh, xnl, DD,
            wih + (size_t)lay * 2 * EDD * DD, wil + (size_t)lay * 2 * EDD * DD, DD,
            part, 2 * EDD, DD, 3, 256);
        if (lay == 0) {
            wconv_kernel<<<2048, 256>>>((const float4*)out_prj,
                (__nv_bfloat162*)woh, (__nv_bfloat162*)wol, NLAY * DD * EDD / 4);
            wconv_kernel<<<1024, 256>>>((const float4*)emb,
                (__nv_bfloat162*)weh, (__nv_bfloat162*)wel, VV * DD / 4);
        }
        reduce_kernel<<<(NTOK * 2 * EDD / 4 + 255) / 256, 256>>>(
            ug, part, NTOK * 2 * EDD / 4, NTOK * 2 * EDD / 4, 3, 0);
        conv_silu_kernel<<<(NTOK * EDD) / 256, 256>>>(
            ug, conv_w + (size_t)lay * EDD * KCV, conv_b + (size_t)lay * EDD,
            uch, ucl);
        gemm_mma<<<gXp, 256, GEMM_SMEM>>>(
            uch, ucl, EDD,
            wxh + (size_t)lay * SPW * EDD, wxl + (size_t)lay * SPW * EDD, EDD,
            part, SPW, EDD, 3, 96);
        reduce_xp_kernel<<<(NTOK * SPW + 255) / 256, 256>>>(sp, part, dth, dtl);
        gemm_mma<<<gDt, 256, GEMM_SMEM>>>(
            dth, dtl, DTR,
            wdh + (size_t)lay * EDD * DTR, wdl + (size_t)lay * EDD * DTR, DTR,
            dtb, EDD, DTR, 0, 64);
        scan2_kernel<<<gScan, 128>>>(
            dtb, dt_b + (size_t)lay * EDD, uch, ucl, sp, ug,
            A_log + (size_t)lay * EDD * NST, Dp + (size_t)lay * EDD, yh, yl);
        gemm_mma<<<gOut, 256, GEMM_SMEM>>>(
            yh, yl, EDD,
            woh + (size_t)lay * DD * EDD, wol + (size_t)lay * DD * EDD, EDD,
            part, DD, EDD, 3, 512);
        reduce_kernel<<<(NTOK * DD / 4 + 255) / 256, 256>>>(
            h, part, NTOK * DD / 4, NTOK * DD / 4, 3, 1);
    }

    rmsnorm2_kernel<<<NTOK, 256>>>(h, normf_w, xnh, xnl);
    gemm_mma<<<gLog, 256, GEMM_SMEM>>>(
        xnh, xnl, DD, weh, wel, DD, part, VV, DD, 3, 384);
    reduce_kernel<<<(NTOK * VV / 4 + 255) / 256, 256>>>(
        out, part, NTOK * VV / 4, NTOK * VV / 4, 2, 2);
}

// round 7
// speedup vs baseline: 3.9443x; 1.0335x over previous
#include <cuda_runtime.h>
#include <cuda_bf16.h>
#include <math.h>
#include <stdint.h>

// Problem dims
#define LL    512
#define BB    2
#define DD    768
#define EDD   1536
#define NST   16
#define KCV   4
#define DTR   48
#define VV    1024
#define NTOK  (LL*BB)   // 1024 tokens, t = b*LL + l
#define NLAY  24
#define SPW   80        // DT_RANK + 2*N

// ---------------------------------------------------------------------------
// Scratch (device globals; no allocation allowed). 256B-aligned for cp.async.
// ---------------------------------------------------------------------------
__device__ __align__(256) float g_h  [NTOK*DD];
__device__ __align__(256) float g_sp [NTOK*SPW];
__device__ __align__(256) float g_dtb[NTOK*EDD];
__device__ __align__(256) float g_pin [3*NTOK*2*EDD];   // in_proj partials
__device__ __align__(256) float g_pxp [16*NTOK*SPW];    // x_proj partials
__device__ __align__(256) float g_pout[3*NTOK*DD];      // out_proj / logits partials

__device__ __align__(256) __nv_bfloat16 g_xnh[NTOK*DD],  g_xnl[NTOK*DD];
__device__ __align__(256) __nv_bfloat16 g_uch[NTOK*EDD], g_ucl[NTOK*EDD];
__device__ __align__(256) __nv_bfloat16 g_dth[NTOK*DTR], g_dtl[NTOK*DTR];
__device__ __align__(256) __nv_bfloat16 g_yh [NTOK*EDD], g_yl [NTOK*EDD];

// Converted weights (hi/lo bf16 split)
__device__ __align__(256) __nv_bfloat16 g_wih[NLAY*2*EDD*DD], g_wil[NLAY*2*EDD*DD];
__device__ __align__(256) __nv_bfloat16 g_wxh[NLAY*SPW*EDD],  g_wxl[NLAY*SPW*EDD];
__device__ __align__(256) __nv_bfloat16 g_wdh[NLAY*EDD*DTR],  g_wdl[NLAY*EDD*DTR];
__device__ __align__(256) __nv_bfloat16 g_woh[NLAY*DD*EDD],   g_wol[NLAY*DD*EDD];
__device__ __align__(256) __nv_bfloat16 g_weh[VV*DD],         g_wel[VV*DD];

// ---------------------------------------------------------------------------
// PTX helpers (arch-agnostic: cp.async / ldmatrix / mma.sync)
// ---------------------------------------------------------------------------
__device__ __forceinline__ uint32_t smem_u32(const void* p) {
    uint32_t a;
    asm("{ .reg .u64 t; cvta.to.shared.u64 t, %1; cvt.u32.u64 %0, t; }"
        : "=r"(a) : "l"(p));
    return a;
}

__device__ __forceinline__ void cp_async16(uint32_t dst, const void* src, uint32_t nbytes) {
    asm volatile("cp.async.cg.shared.global [%0], [%1], 16, %2;"
                 :: "r"(dst), "l"(src), "r"(nbytes) : "memory");
}
#define CP_COMMIT() asm volatile("cp.async.commit_group;" ::: "memory")
#define CP_WAIT1()  asm volatile("cp.async.wait_group 1;" ::: "memory")
#define CP_WAIT0()  asm volatile("cp.async.wait_group 0;" ::: "memory")

__device__ __forceinline__ void ldm_x4(uint32_t* r, uint32_t addr) {
    asm volatile("ldmatrix.sync.aligned.m8n8.x4.shared.b16 {%0,%1,%2,%3}, [%4];"
                 : "=r"(r[0]), "=r"(r[1]), "=r"(r[2]), "=r"(r[3]) : "r"(addr));
}

__device__ __forceinline__ void mma16816(float* d, const uint32_t* a, const uint32_t* b) {
    asm volatile(
        "mma.sync.aligned.m16n8k16.row.col.f32.bf16.bf16.f32 "
        "{%0,%1,%2,%3}, {%4,%5,%6,%7}, {%8,%9}, {%0,%1,%2,%3};"
        : "+f"(d[0]), "+f"(d[1]), "+f"(d[2]), "+f"(d[3])
        : "r"(a[0]), "r"(a[1]), "r"(a[2]), "r"(a[3]), "r"(b[0]), "r"(b[1]));
}

// ---------------------------------------------------------------------------
// mma.sync GEMM, bf16x3 compensated: C[M,N] = A[M,K] * W[N,K]^T (fp32-class)
// 128x128 CTA tile, K chunks of 32, 2-stage cp.async pipeline, 2 CTAs/SM.
// Split-K via blockIdx.z (klen of K each; partial z at C + z*NTOK*N).
// mode 0: store; 2: logits permute; 3: partial store (split-K).
// ---------------------------------------------------------------------------
#define TILE_B   10240            // 128 rows * 80B
#define BUF_B    (4*TILE_B)       // Ah, Al, Wh, Wl
#define GEMM_SMEM (2*BUF_B)       // 2 stages = 81920

__global__ void __launch_bounds__(256, 2) gemm_mma(
    const __nv_bfloat16* __restrict__ Ah, const __nv_bfloat16* __restrict__ Al, int lda,
    const __nv_bfloat16* __restrict__ Wh, const __nv_bfloat16* __restrict__ Wl, int ldw,
    float* __restrict__ C, int N, int K, int mode, int klen)
{
    extern __shared__ char smem[];
    const uint32_t sb = smem_u32(smem);
    const int tid  = threadIdx.x;
    const int lane = tid & 31;
    const int wid  = tid >> 5;
    const int wm   = wid & 3;        // 0..3  -> 32-row slice
    const int wn   = wid >> 2;       // 0..1  -> 64-col slice
    const int bm = blockIdx.y * 128;
    const int bn = blockIdx.x * 128;
    const int koff = blockIdx.z * klen;
    const int kend = min(koff + klen, K);
    const int nc = (kend - koff + 31) >> 5;
    if (mode == 3) C += (size_t)blockIdx.z * NTOK * N;

    float acc[2][8][4];
#pragma unroll
    for (int i = 0; i < 2; i++)
#pragma unroll
        for (int j = 0; j < 8; j++)
#pragma unroll
            for (int k = 0; k < 4; k++) acc[i][j][k] = 0.f;

    // Chunk-invariant load precompute: 8 cp.async per thread per chunk.
    const int seg = tid & 3;              // 16B segment within 64-elem row chunk
    const int r0  = tid >> 2;             // 0..63
    const __nv_bfloat16* gsrc[8];
    uint32_t dsto[8];
    bool rowok[8];
#pragma unroll
    for (int i = 0; i < 8; i++) {
        const int tile = i >> 1;
        const int row  = (i & 1) * 64 + r0;
        const __nv_bfloat16* s; int gr, ld; bool rk;
        if (tile == 0)      { s = Ah; gr = bm + row; ld = lda; rk = true; }
        else if (tile == 1) { s = Al; gr = bm + row; ld = lda; rk = true; }
        else if (tile == 2) { s = Wh; gr = bn + row; ld = ldw; rk = (bn + row) < N; }
        else                { s = Wl; gr = bn + row; ld = ldw; rk = (bn + row) < N; }
        gsrc[i]  = s + (size_t)gr * ld + koff + seg * 8;
        dsto[i]  = (uint32_t)(tile * TILE_B + row * 80 + seg * 16);
        rowok[i] = rk;
    }
    const int kseg0 = koff + seg * 8;

    auto issue = [&](int c, int buf) {
        const int kk = kseg0 + (c << 5);
        const bool kok = kk < kend;
        const uint32_t base = sb + buf * BUF_B;
#pragma unroll
        for (int i = 0; i < 8; i++) {
            bool ok = rowok[i] && kok;
            cp_async16(base + dsto[i],
                       ok ? (const void*)(gsrc[i] + (c << 5)) : (const void*)Ah,
                       ok ? 16u : 0u);
        }
    };

    issue(0, 0); CP_COMMIT();

    for (int c = 0; c < nc; c++) {
        const int buf = c & 1;
        if (c + 1 < nc) { issue(c + 1, buf ^ 1); CP_COMMIT(); CP_WAIT1(); }
        else            { CP_WAIT0(); }
        __syncthreads();

        const uint32_t bA = sb + buf * BUF_B;
        const uint32_t bW = bA + 2 * TILE_B;
        const int q = lane >> 3, l8 = lane & 7;

#pragma unroll
        for (int ks = 0; ks < 2; ks++) {
            const int k = ks << 4;
            uint32_t ah[2][4], al_[2][4];
#pragma unroll
            for (int mt = 0; mt < 2; mt++) {
                uint32_t off = (uint32_t)((wm * 32 + mt * 16 + l8 + (q & 1) * 8) * 80
                                          + (k + (q >> 1) * 8) * 2);
                ldm_x4(ah[mt],  bA + off);
                ldm_x4(al_[mt], bA + TILE_B + off);
            }
#pragma unroll
            for (int np = 0; np < 4; np++) {
                uint32_t bh4[4], bl4[4];
                uint32_t off = (uint32_t)((wn * 64 + np * 16 + l8 + (q >> 1) * 8) * 80
                                          + (k + (q & 1) * 8) * 2);
                ldm_x4(bh4, bW + off);
                ldm_x4(bl4, bW + TILE_B + off);
#pragma unroll
                for (int mt = 0; mt < 2; mt++) {
                    mma16816(acc[mt][2 * np],     ah[mt],  &bh4[0]);
                    mma16816(acc[mt][2 * np + 1], ah[mt],  &bh4[2]);
                    mma16816(acc[mt][2 * np],     ah[mt],  &bl4[0]);
                    mma16816(acc[mt][2 * np + 1], ah[mt],  &bl4[2]);
                    mma16816(acc[mt][2 * np],     al_[mt], &bh4[0]);
                    mma16816(acc[mt][2 * np + 1], al_[mt], &bh4[2]);
                }
            }
        }
        __syncthreads();
    }

    // Epilogue
    const int tr = lane >> 2, tc = (lane & 3) * 2;
#pragma unroll
    for (int mt = 0; mt < 2; mt++) {
#pragma unroll
        for (int nt = 0; nt < 8; nt++) {
            float* a4 = acc[mt][nt];
            int r0e = bm + wm * 32 + mt * 16 + tr;
            int c0 = bn + wn * 64 + nt * 8 + tc;
#pragma unroll
            for (int half = 0; half < 2; half++) {
                int row = r0e + half * 8;
                float v0 = a4[half * 2], v1 = a4[half * 2 + 1];
                if (mode == 2) {
                    int lr = row & (LL - 1), br = row >> 9;
                    size_t base = (size_t)lr * (BB * VV) + (size_t)br * VV;
                    if (c0 < N)     C[base + c0]     = v0;
                    if (c0 + 1 < N) C[base + c0 + 1] = v1;
                } else {
                    if (c0 < N)     C[(size_t)row * N + c0]     = v0;
                    if (c0 + 1 < N) C[(size_t)row * N + c0 + 1] = v1;
                }
            }
        }
    }
}

// ---------------------------------------------------------------------------
// Generic split-K reduce (used for final logits only).
// mode 2: logits permute ([t][v] -> out[l][b][v]).
// ---------------------------------------------------------------------------
__global__ void reduce_kernel(float* __restrict__ dst,
                              const float* __restrict__ part,
                              int n4, int stride4, int ns, int mode)
{
    int i = blockIdx.x * blockDim.x + threadIdx.x;
    if (i >= n4) return;
    const float4* p4 = (const float4*)part;
    float4 s = p4[i];
    for (int k = 1; k < ns; k++) {
        float4 v = p4[i + (size_t)k * stride4];
        s.x += v.x; s.y += v.y; s.z += v.z; s.w += v.w;
    }
    if (mode == 2) {
        int idx = i << 2;
        int t = idx >> 10, v = idx & (VV - 1);
        int l = t & (LL - 1), b = t >> 9;
        ((float4*)(dst + (size_t)l * (BB * VV) + (size_t)b * VV + v))[0] = s;
    } else {
        ((float4*)dst)[i] = s;
    }
}

// Fused out_proj reduce + residual + RMSNorm + bf16 split (one block per token)
__global__ void reduce_rms_kernel(float* __restrict__ h,
                                  const float* __restrict__ part,
                                  const float* __restrict__ w,
                                  __nv_bfloat16* __restrict__ oh,
                                  __nv_bfloat16* __restrict__ ol)
{
    const int t = blockIdx.x;
    float vals[3];
    float s = 0.f;
#pragma unroll
    for (int j = 0; j < 3; j++) {
        int i = threadIdx.x + j * 256;
        size_t o = (size_t)t * DD + i;
        float v = h[o] + part[o] + part[o + (size_t)NTOK * DD]
                       + part[o + 2 * (size_t)NTOK * DD];
        vals[j] = v;
        h[o] = v;
        s += v * v;
    }
    __shared__ float red[256];
    red[threadIdx.x] = s;
    __syncthreads();
    for (int off = 128; off > 0; off >>= 1) {
        if (threadIdx.x < off) red[threadIdx.x] += red[threadIdx.x + off];
        __syncthreads();
    }
    float scale = rsqrtf(red[0] / (float)DD + 1e-5f);
#pragma unroll
    for (int j = 0; j < 3; j++) {
        int i = threadIdx.x + j * 256;
        float v = vals[j] * scale * w[i];
        __nv_bfloat16 hv = __float2bfloat16(v);
        oh[(size_t)t * DD + i] = hv;
        ol[(size_t)t * DD + i] = __float2bfloat16(v - __bfloat162float(hv));
    }
}

// xp reduce: sp[1024][80] = sum of 16 partials; also emit dt_r bf16 hi/lo.
__global__ void reduce_xp_kernel(float* __restrict__ sp,
                                 const float* __restrict__ part,
                                 __nv_bfloat16* __restrict__ dth,
                                 __nv_bfloat16* __restrict__ dtl)
{
    int i = blockIdx.x * blockDim.x + threadIdx.x;
    if (i >= NTOK * SPW) return;
    float s = part[i];
#pragma unroll
    for (int k = 1; k < 16; k++) s += part[i + k * (NTOK * SPW)];
    sp[i] = s;
    int col = i % SPW;
    if (col < DTR) {
        int t = i / SPW;
        __nv_bfloat16 hv = __float2bfloat16(s);
        dth[(size_t)t * DTR + col] = hv;
        dtl[(size_t)t * DTR + col] = __float2bfloat16(s - __bfloat162float(hv));
    }
}

// ---------------------------------------------------------------------------
// Weight fp32 -> bf16 hi/lo conversion (vectorized)
// ---------------------------------------------------------------------------
__global__ void wconv_kernel(const float4* __restrict__ s,
                             __nv_bfloat162* __restrict__ h,
                             __nv_bfloat162* __restrict__ l, int n4)
{
    for (int i = blockIdx.x * blockDim.x + threadIdx.x; i < n4;
         i += gridDim.x * blockDim.x) {
        float4 v = s[i];
        __nv_bfloat16 h0 = __float2bfloat16(v.x), h1 = __float2bfloat16(v.y);
        __nv_bfloat16 h2 = __float2bfloat16(v.z), h3 = __float2bfloat16(v.w);
        h[2 * i]     = __nv_bfloat162(h0, h1);
        h[2 * i + 1] = __nv_bfloat162(h2, h3);
        l[2 * i]     = __nv_bfloat162(
            __float2bfloat16(v.x - __bfloat162float(h0)),
            __float2bfloat16(v.y - __bfloat162float(h1)));
        l[2 * i + 1] = __nv_bfloat162(
            __float2bfloat16(v.z - __bfloat162float(h2)),
            __float2bfloat16(v.w - __bfloat162float(h3)));
    }
}

// ---------------------------------------------------------------------------
// Embedding gather
// ---------------------------------------------------------------------------
__global__ void embed_kernel(const int* __restrict__ src,
                             const float* __restrict__ emb,
                             float* __restrict__ h)
{
    int t = blockIdx.x;
    int b = t >> 9, l = t & (LL - 1);
    int id = src[l * BB + b];
    const float* er = emb + (size_t)id * DD;
    float* hr = h + (size_t)t * DD;
    for (int i = threadIdx.x; i < DD; i += 256) hr[i] = er[i];
}

// ---------------------------------------------------------------------------
// RMSNorm -> bf16 hi/lo outputs (standalone, layer 0 only)
// ---------------------------------------------------------------------------
__global__ void rmsnorm2_kernel(const float* __restrict__ x,
                                const float* __restrict__ w,
                                __nv_bfloat16* __restrict__ oh,
                                __nv_bfloat16* __restrict__ ol)
{
    int t = blockIdx.x;
    const float* xr = x + (size_t)t * DD;
    float s = 0.f;
    for (int i = threadIdx.x; i < DD; i += 256) { float v = xr[i]; s += v * v; }
    __shared__ float red[256];
    red[threadIdx.x] = s;
    __syncthreads();
    for (int off = 128; off > 0; off >>= 1) {
        if (threadIdx.x < off) red[threadIdx.x] += red[threadIdx.x + off];
        __syncthreads();
    }
    float scale = rsqrtf(red[0] / (float)DD + 1e-5f);
    for (int i = threadIdx.x; i < DD; i += 256) {
        float v = xr[i] * scale * w[i];
        __nv_bfloat16 hv = __float2bfloat16(v);
        oh[(size_t)t * DD + i] = hv;
        ol[(size_t)t * DD + i] = __float2bfloat16(v - __bfloat162float(hv));
    }
}

// ---------------------------------------------------------------------------
// Depthwise causal conv (K=4) + SiLU, reading 3 split-K partials -> bf16 hi/lo
// ---------------------------------------------------------------------------
__global__ void conv_silu_kernel(const float* __restrict__ pin,
                                 const float* __restrict__ cw,
                                 const float* __restrict__ cb,
                                 __nv_bfloat16* __restrict__ uh,
                                 __nv_bfloat16* __restrict__ ul)
{
    const size_t P = (size_t)NTOK * 2 * EDD;
    int idx = blockIdx.x * blockDim.x + threadIdx.x;
    if (idx >= NTOK * EDD) return;
    int t = idx / EDD, e = idx - t * EDD;
    int l = t & (LL - 1);
    const float* base = pin + (size_t)t * (2 * EDD) + e;
    float4 w = *(const float4*)(cw + (size_t)e * KCV);
    float acc = cb[e];
#pragma unroll
    for (int tap = 0; tap < 4; tap++) {
        if (l >= 3 - tap) {
            const float* p = base - (3 - tap) * (2 * EDD);
            float v = p[0] + p[P] + p[2 * P];
            acc += v * ((const float*)&w)[tap];
        }
    }
    float s = 1.f / (1.f + __expf(-acc));
    float v = acc * s;
    __nv_bfloat16 hv = __float2bfloat16(v);
    uh[idx] = hv;
    ul[idx] = __float2bfloat16(v - __bfloat162float(hv));
}

// ---------------------------------------------------------------------------
// Selective scan: smem-staged 64-step windows, softplus fused, bf16 out.
// Gate read directly from the 3 in_proj partials.
// Block = 128 threads, 32 channels (e), 4 threads/channel (q = N-split).
// ---------------------------------------------------------------------------
__global__ void __launch_bounds__(128) scan2_kernel(
    const float* __restrict__ dtraw,
    const float* __restrict__ dtbias,
    const __nv_bfloat16* __restrict__ uch,
    const __nv_bfloat16* __restrict__ ucl,
    const float* __restrict__ sp,
    const float* __restrict__ pin,
    const float* __restrict__ A_log,
    const float* __restrict__ Dp,
    __nv_bfloat16* __restrict__ yh,
    __nv_bfloat16* __restrict__ yl)
{
    __shared__ float  sdt[64][32], suc[64][32], sg[64][32];
    __shared__ float4 sB[64][4], sC[64][4];

    const size_t P = (size_t)NTOK * 2 * EDD;
    const int b  = blockIdx.y;
    const int eb = blockIdx.x * 32;
    const int tid = threadIdx.x;
    const int q = tid & 3, er = tid >> 2;
    const int e = eb + er;

    float4 al = *(const float4*)(A_log + (size_t)e * NST + q * 4);
    float a0 = -__expf(al.x), a1 = -__expf(al.y),
          a2 = -__expf(al.z), a3 = -__expf(al.w);
    const float dD  = Dp[e];
    const float bsv = dtbias[e];

    float h0 = 0.f, h1 = 0.f, h2 = 0.f, h3 = 0.f;

    for (int w = 0; w < 8; w++) {
        const int t0 = b * LL + w * 64;
#pragma unroll
        for (int i = 0; i < 16; i++) {
            int idx = tid + i * 128;
            int s = idx >> 5, j = idx & 31;
            size_t tr = (size_t)(t0 + s);
            sdt[s][j] = dtraw[tr * EDD + eb + j];
            suc[s][j] = __bfloat162float(uch[tr * EDD + eb + j])
                      + __bfloat162float(ucl[tr * EDD + eb + j]);
            const float* gp = pin + tr * (2 * EDD) + EDD + eb + j;
            sg[s][j] = gp[0] + gp[P] + gp[2 * P];
            float v = sp[tr * SPW + DTR + j];
            if (j < 16) ((float*)&sB[s][0])[j]      = v;
            else        ((float*)&sC[s][0])[j - 16] = v;
        }
        __syncthreads();
#pragma unroll 4
        for (int s = 0; s < 64; s++) {
            float x = sdt[s][er] + bsv;
            float dtv = (x > 15.f) ? x : log1pf(__expf(x));
            float u = suc[s][er];
            float4 Bv = sB[s][q], Cv = sC[s][q];
            float du = dtv * u;
            h0 = __expf(dtv * a0) * h0 + du * Bv.x;
            h1 = __expf(dtv * a1) * h1 + du * Bv.y;
            h2 = __expf(dtv * a2) * h2 + du * Bv.z;
            h3 = __expf(dtv * a3) * h3 + du * Bv.w;
            float ys = h0 * Cv.x + h1 * Cv.y + h2 * Cv.z + h3 * Cv.w;
            ys += __shfl_xor_sync(0xffffffffu, ys, 1);
            ys += __shfl_xor_sync(0xffffffffu, ys, 2);
            if (q == 0) {
                float gv = sg[s][er];
                float yv = (ys + u * dD) * (gv / (1.f + __expf(-gv)));
                __nv_bfloat16 hv = __float2bfloat16(yv);
                size_t o = (size_t)(t0 + s) * EDD + e;
                yh[o] = hv;
                yl[o] = __float2bfloat16(yv - __bfloat162float(hv));
            }
        }
        __syncthreads();
    }
}

// ---------------------------------------------------------------------------
extern "C" void kernel_launch(void* const* d_in, const int* in_sizes, int n_in,
                              void* d_out, int out_size)
{
    const int*   src     = (const int*)  d_in[0];
    const float* emb     = (const float*)d_in[1];
    const float* norm_w  = (const float*)d_in[2];
    const float* in_proj = (const float*)d_in[3];
    const float* conv_w  = (const float*)d_in[4];
    const float* conv_b  = (const float*)d_in[5];
    const float* x_proj  = (const float*)d_in[6];
    const float* dt_w    = (const float*)d_in[7];
    const float* dt_b    = (const float*)d_in[8];
    const float* A_log   = (const float*)d_in[9];
    const float* Dp      = (const float*)d_in[10];
    const float* out_prj = (const float*)d_in[11];
    const float* normf_w = (const float*)d_in[12];
    float* out = (float*)d_out;
    (void)in_sizes; (void)n_in; (void)out_size;

    cudaFuncSetAttribute(gemm_mma,
                         cudaFuncAttributeMaxDynamicSharedMemorySize, GEMM_SMEM);

    float *h, *sp, *dtb, *pin, *pxp, *pout;
    __nv_bfloat16 *xnh, *xnl, *uch, *ucl, *dth, *dtl, *yh, *yl;
    __nv_bfloat16 *wih, *wil, *wxh, *wxl, *wdh, *wdl, *woh, *wol, *weh, *wel;
    cudaGetSymbolAddress((void**)&h,    g_h);
    cudaGetSymbolAddress((void**)&sp,   g_sp);
    cudaGetSymbolAddress((void**)&dtb,  g_dtb);
    cudaGetSymbolAddress((void**)&pin,  g_pin);
    cudaGetSymbolAddress((void**)&pxp,  g_pxp);
    cudaGetSymbolAddress((void**)&pout, g_pout);
    cudaGetSymbolAddress((void**)&xnh, g_xnh);
    cudaGetSymbolAddress((void**)&xnl, g_xnl);
    cudaGetSymbolAddress((void**)&uch, g_uch);
    cudaGetSymbolAddress((void**)&ucl, g_ucl);
    cudaGetSymbolAddress((void**)&dth, g_dth);
    cudaGetSymbolAddress((void**)&dtl, g_dtl);
    cudaGetSymbolAddress((void**)&yh,  g_yh);
    cudaGetSymbolAddress((void**)&yl,  g_yl);
    cudaGetSymbolAddress((void**)&wih, g_wih);
    cudaGetSymbolAddress((void**)&wil, g_wil);
    cudaGetSymbolAddress((void**)&wxh, g_wxh);
    cudaGetSymbolAddress((void**)&wxl, g_wxl);
    cudaGetSymbolAddress((void**)&wdh, g_wdh);
    cudaGetSymbolAddress((void**)&wdl, g_wdl);
    cudaGetSymbolAddress((void**)&woh, g_woh);
    cudaGetSymbolAddress((void**)&wol, g_wol);
    cudaGetSymbolAddress((void**)&weh, g_weh);
    cudaGetSymbolAddress((void**)&wel, g_wel);

    const dim3 gIn (2 * EDD / 128, NTOK / 128, 3);   // N=3072, klen 256
    const dim3 gXp (1,             NTOK / 128, 16);  // N=80,   klen 96
    const dim3 gDt (EDD / 128,     NTOK / 128, 1);   // N=1536, K=48
    const dim3 gOut(DD / 128,      NTOK / 128, 3);   // N=768,  klen 512
    const dim3 gLog(VV / 128,      NTOK / 128, 2);   // N=1024, klen 384
    const dim3 gScan(EDD / 32, BB);

    // Launch order: my launch #4 is the in_proj GEMM (profiled by ncu -s5).
    embed_kernel<<<NTOK, 256>>>(src, emb, h);                                   // 1
    wconv_kernel<<<2048, 256>>>((const float4*)in_proj,
        (__nv_bfloat162*)wih, (__nv_bfloat162*)wil, NLAY * 2 * EDD * DD / 4);   // 2
    rmsnorm2_kernel<<<NTOK, 256>>>(h, norm_w, xnh, xnl);                        // 3

    for (int lay = 0; lay < NLAY; lay++) {
        gemm_mma<<<gIn, 256, GEMM_SMEM>>>(                                      // 4 <- profiled
            xnh, xnl, DD,
            wih + (size_t)lay * 2 * EDD * DD, wil + (size_t)lay * 2 * EDD * DD, DD,
            pin, 2 * EDD, DD, 3, 256);
        if (lay == 0) {
            wconv_kernel<<<1024, 256>>>((const float4*)x_proj,
                (__nv_bfloat162*)wxh, (__nv_bfloat162*)wxl, NLAY * SPW * EDD / 4);
            wconv_kernel<<<1024, 256>>>((const float4*)dt_w,
                (__nv_bfloat162*)wdh, (__nv_bfloat162*)wdl, NLAY * EDD * DTR / 4);
            wconv_kernel<<<2048, 256>>>((const float4*)out_prj,
                (__nv_bfloat162*)woh, (__nv_bfloat162*)wol, NLAY * DD * EDD / 4);
            wconv_kernel<<<1024, 256>>>((const float4*)emb,
                (__nv_bfloat162*)weh, (__nv_bfloat162*)wel, VV * DD / 4);
        }
        conv_silu_kernel<<<(NTOK * EDD) / 256, 256>>>(
            pin, conv_w + (size_t)lay * EDD * KCV, conv_b + (size_t)lay * EDD,
            uch, ucl);
        gemm_mma<<<gXp, 256, GEMM_SMEM>>>(
            uch, ucl, EDD,
            wxh + (size_t)lay * SPW * EDD, wxl + (size_t)lay * SPW * EDD, EDD,
            pxp, SPW, EDD, 3, 96);
        reduce_xp_kernel<<<(NTOK * SPW + 255) / 256, 256>>>(sp, pxp, dth, dtl);
        gemm_mma<<<gDt, 256, GEMM_SMEM>>>(
            dth, dtl, DTR,
            wdh + (size_t)lay * EDD * DTR, wdl + (size_t)lay * EDD * DTR, DTR,
            dtb, EDD, DTR, 0, 64);
        scan2_kernel<<<gScan, 128>>>(
            dtb, dt_b + (size_t)lay * EDD, uch, ucl, sp, pin,
            A_log + (size_t)lay * EDD * NST, Dp + (size_t)lay * EDD, yh, yl);
        gemm_mma<<<gOut, 256, GEMM_SMEM>>>(
            yh, yl, EDD,
            woh + (size_t)lay * DD * EDD, wol + (size_t)lay * DD * EDD, EDD,
            pout, DD, EDD, 3, 512);
        reduce_rms_kernel<<<NTOK, 256>>>(
            h, pout,
            (lay + 1 < NLAY) ? (norm_w + (size_t)(lay + 1) * DD) : normf_w,
            xnh, xnl);
    }

    gemm_mma<<<gLog, 256, GEMM_SMEM>>>(
        xnh, xnl, DD, weh, wel, DD, pout, VV, DD, 3, 384);
    reduce_kernel<<<(NTOK * VV / 4 + 255) / 256, 256>>>(
        out, pout, NTOK * VV / 4, NTOK * VV / 4, 2, 2);
}